// round 14
// baseline (speedup 1.0000x reference)
#include <cuda_runtime.h>
#include <cuda_fp16.h>
#include <math.h>

#define D 128
#define MAXN 65536
#define MAXE 1100000

// Scratch (allocation-free rule: __device__ globals)
__device__ __half2  g_xt16[MAXN * (D / 2)];
__device__ __half2  g_xl16[MAXN * (D / 2)];
__device__ int      g_deg[MAXN];
__device__ int      g_cursor[MAXN];
__device__ int      g_incl[MAXN];
__device__ int      g_bsum[512];
__device__ int      g_csr[MAXE];
__device__ unsigned g_rowcur;
__device__ unsigned g_done;

__device__ __forceinline__ float warp_sum(float v) {
#pragma unroll
    for (int o = 16; o; o >>= 1) v += __shfl_xor_sync(0xFFFFFFFFu, v, o);
    return v;
}

__device__ __forceinline__ float clip_c(float c) {
    return fminf(fmaxf(c, 0.1f), 10.0f);
}

__device__ __forceinline__ unsigned smem_u32(const void* p) {
    return (unsigned)__cvta_generic_to_shared(p);
}

// Per-block edge-index dtype detection: read first 64 int64 words; if any is
// outside [0,N) the buffer is int32 (misdetect needs 64 consecutive zero
// high-words: p=(1/N)^64 ~ 0). Returns 1 if int64.
__device__ __forceinline__ int detect_is64(const void* ei, int E, long long N) {
    const long long* p64 = (const long long*)ei;
    int n = 2 * E < 128 ? E : 64;
    int bad = 0;
    for (int i = threadIdx.x; i < n; i += 256) {
        long long v = p64[i];
        if (v < 0 || v >= N) bad = 1;
    }
    return !__syncthreads_or(bad);
}

// ---------------------------------------------------------------------------
// In-degree histogram straight from ei (inline dtype detection).
// deg/cursor are pre-zeroed by the PREVIOUS execution's k_scanA (static-init
// zero on the first execution) -> deterministic every replay.
// ---------------------------------------------------------------------------
__global__ void k_hist(const void* __restrict__ ei, int* __restrict__ deg,
                       int E, int N) {
    int is64 = detect_is64(ei, E, (long long)N);
    int e = blockIdx.x * blockDim.x + threadIdx.x;
    if (e >= E) return;
    long long d;
    if (is64) d = ((const long long*)ei)[(size_t)E + e];
    else      d = (long long)((const int*)ei)[(size_t)E + e];
    int di = (int)min(max(d, 0LL), (long long)(N - 1));
    atomicAdd(&deg[di], 1);
}

// ---------------------------------------------------------------------------
// Prefix scan with fused block-sum scan (last-block pattern): per-block
// inclusive scan into incl + block sums into bsum; the LAST block to finish
// scans bsum in place (exclusive) and resets the done counter.
// scanA also re-zeroes deg and cursor so no memset pass.
// rowstart reconstructed by readers: rowstart[g+1] = incl[g] + bsum[g>>8].
// ---------------------------------------------------------------------------
__global__ void k_scanA(int* __restrict__ deg, int* __restrict__ incl,
                        int* __restrict__ bsum, int* __restrict__ cursor,
                        int N, int nb) {
    __shared__ int wsum[8];
    __shared__ bool isLast;
    int tid = threadIdx.x, lane = tid & 31, warp = tid >> 5;
    int gid = blockIdx.x * 256 + tid;
    int v = (gid < N) ? deg[gid] : 0;
    int x = v;
#pragma unroll
    for (int o = 1; o < 32; o <<= 1) {
        int y = __shfl_up_sync(0xFFFFFFFFu, x, o);
        if (lane >= o) x += y;
    }
    if (lane == 31) wsum[warp] = x;
    __syncthreads();
    if (warp == 0) {
        int s = (lane < 8) ? wsum[lane] : 0;
        int y = s;
#pragma unroll
        for (int o = 1; o < 8; o <<= 1) {
            int z = __shfl_up_sync(0xFFFFFFFFu, y, o);
            if (lane >= o) y += z;
        }
        if (lane < 8) wsum[lane] = y - s;   // exclusive warp offset
    }
    __syncthreads();
    int inclv = x + wsum[warp];
    if (gid < N) {
        incl[gid] = inclv;
        deg[gid] = 0;      // pre-zero for next execution's k_hist
        cursor[gid] = 0;   // pre-zero for this execution's k_fill
    }
    if (tid == 255) bsum[blockIdx.x] = inclv;

    // --- last-block tail: scan bsum[0..nb) exclusive, in place ---
    __threadfence();
    if (tid == 0) {
        unsigned prev = atomicAdd(&g_done, 1u);
        isLast = (prev == (unsigned)(gridDim.x - 1));
    }
    __syncthreads();
    if (!isLast) return;
    if (tid == 0) g_done = 0u;   // reset for next replay (deterministic)

    int bv = (tid < nb) ? bsum[tid] : 0;
    int bx = bv;
#pragma unroll
    for (int o = 1; o < 32; o <<= 1) {
        int y = __shfl_up_sync(0xFFFFFFFFu, bx, o);
        if (lane >= o) bx += y;
    }
    __syncthreads();   // reuse wsum
    if (lane == 31) wsum[warp] = bx;
    __syncthreads();
    if (warp == 0) {
        int s = (lane < 8) ? wsum[lane] : 0;
        int y = s;
#pragma unroll
        for (int o = 1; o < 8; o <<= 1) {
            int z = __shfl_up_sync(0xFFFFFFFFu, y, o);
            if (lane >= o) y += z;
        }
        if (lane < 8) wsum[lane] = y - s;
    }
    __syncthreads();
    if (tid < nb) bsum[tid] = bx + wsum[warp] - bv;   // exclusive block offset
}

// ---------------------------------------------------------------------------
// CSR fill straight from ei (inline dtype detection, clamped), rowstart inline.
// ---------------------------------------------------------------------------
__global__ void k_fill(const void* __restrict__ ei,
                       const int* __restrict__ incl, const int* __restrict__ bsum,
                       int* __restrict__ cursor, int* __restrict__ csr,
                       int E, int N) {
    int is64 = detect_is64(ei, E, (long long)N);
    int e = blockIdx.x * blockDim.x + threadIdx.x;
    if (e >= E) return;
    long long s, d;
    if (is64) {
        const long long* p = (const long long*)ei;
        s = p[e];
        d = p[(size_t)E + e];
    } else {
        const int* p = (const int*)ei;
        s = p[e];
        d = p[(size_t)E + e];
    }
    int si = (int)min(max(s, 0LL), (long long)(N - 1));
    int di = (int)min(max(d, 0LL), (long long)(N - 1));
    int rs = (di > 0) ? (incl[di - 1] + bsum[(di - 1) >> 8]) : 0;
    int pos = rs + atomicAdd(&cursor[di], 1);
    csr[pos] = si;
}

// ---------------------------------------------------------------------------
// Fused (logmap+) HMMA GEMM.
// first=1: load fp32 x_hyp, apply logmap, write xt16 + As.
// first=0: load fp16 xt16 (already the tangent vector) straight into As.
// Block: 128 rows x 128 cols, 8 warps; Bs pitch 40 halves (conflict-free);
// W register-prefetch; B fragments via ldmatrix.x4.
// Block 0 thread 0 also resets the agg row cursor.
// ---------------------------------------------------------------------------
__global__ void __launch_bounds__(256) k_gemm_fused(
        const float* __restrict__ xin, const float* __restrict__ W,
        const float* __restrict__ b, __half2* __restrict__ xt16,
        __half2* __restrict__ xl16, const float* __restrict__ curv,
        int l, int N, int first) {
    __shared__ __half As[128][136];   // 34816 B
    __shared__ __half Bs[128][40];    // 10240 B  (total 44 KB)
    int tid = threadIdx.x;
    int lane = tid & 31;
    int wid = tid >> 5;
    int row0 = blockIdx.x * 128;
    int m0 = wid * 16;

    if (blockIdx.x == 0 && tid == 0) g_rowcur = 0u;   // reset agg cursor

    if (first) {
        float c = clip_c(curv[l]);
        float K = 1.0f / c;
        float sqrtK = sqrtf(K);
#pragma unroll
        for (int i = 0; i < 16; i++) {
            int row = m0 + i;
            int grow = row0 + row;
            float4 v = make_float4(0.f, 0.f, 0.f, 0.f);
            if (grow < N)
                v = __ldg(reinterpret_cast<const float4*>(xin + (size_t)grow * D) + lane);
            float ss = v.x * v.x + v.y * v.y + v.z * v.z + v.w * v.w;
            ss = warp_sum(ss);
            float xnorm = sqrtf(ss);
            float t = sqrtf(K + ss);
            float theta = acoshf(fmaxf(t / sqrtK, 1.0f + 1e-7f));
            float s = sqrtK * theta / fmaxf(xnorm, 1e-7f);
            v.x *= s; v.y *= s; v.z *= s; v.w *= s;
            __half2 h0 = __float22half2_rn(make_float2(v.x, v.y));
            __half2 h1 = __float22half2_rn(make_float2(v.z, v.w));
            uint2 u;
            u.x = *reinterpret_cast<unsigned*>(&h0);
            u.y = *reinterpret_cast<unsigned*>(&h1);
            if (grow < N)
                *reinterpret_cast<uint2*>(xt16 + (size_t)grow * (D / 2) + lane * 2) = u;
            *reinterpret_cast<uint2*>(&As[row][lane * 4]) = u;
        }
    } else {
#pragma unroll
        for (int i = 0; i < 16; i++) {
            int row = m0 + i;
            int grow = row0 + row;
            uint2 u = make_uint2(0u, 0u);
            if (grow < N)
                u = __ldg(reinterpret_cast<const uint2*>(
                    xt16 + (size_t)grow * (D / 2)) + lane);
            *reinterpret_cast<uint2*>(&As[row][lane * 4]) = u;
        }
    }

    float acc[16][4];
#pragma unroll
    for (int nt = 0; nt < 16; nt++)
#pragma unroll
        for (int q = 0; q < 4; q++) acc[nt][q] = 0.0f;

    // ldmatrix lane address components
    int a_rr = lane & 7;
    int a_sel = lane >> 3;                  // 0..3
    int a_row = m0 + a_rr + ((a_sel & 1) ? 8 : 0);
    int a_koff = (a_sel >> 1) ? 8 : 0;
    int b_row2 = (lane & 7) + ((lane & 16) ? 8 : 0);
    int b_col2 = (lane & 8) ? 8 : 0;

    // W staging assignment: thread -> row j, k-half
    int wj = tid >> 1;
    int wkh = (tid & 1) * 16;

    // prefetch W chunk 0 into registers
    float4 wreg[4];
    {
        const float4* wp = reinterpret_cast<const float4*>(&W[(size_t)wj * D + wkh]);
#pragma unroll
        for (int p = 0; p < 4; p++) wreg[p] = __ldg(wp + p);
    }

    for (int kc = 0; kc < 4; kc++) {
        __syncthreads();   // previous Bs consumed; kc=0 also covers As writes
        // store registered W chunk to Bs (fp16)
        {
            __half2 h0 = __float22half2_rn(make_float2(wreg[0].x, wreg[0].y));
            __half2 h1 = __float22half2_rn(make_float2(wreg[0].z, wreg[0].w));
            __half2 h2 = __float22half2_rn(make_float2(wreg[1].x, wreg[1].y));
            __half2 h3 = __float22half2_rn(make_float2(wreg[1].z, wreg[1].w));
            __half2 h4 = __float22half2_rn(make_float2(wreg[2].x, wreg[2].y));
            __half2 h5 = __float22half2_rn(make_float2(wreg[2].z, wreg[2].w));
            __half2 h6 = __float22half2_rn(make_float2(wreg[3].x, wreg[3].y));
            __half2 h7 = __float22half2_rn(make_float2(wreg[3].z, wreg[3].w));
            uint4 u0, u1;
            u0.x = *reinterpret_cast<unsigned*>(&h0);
            u0.y = *reinterpret_cast<unsigned*>(&h1);
            u0.z = *reinterpret_cast<unsigned*>(&h2);
            u0.w = *reinterpret_cast<unsigned*>(&h3);
            u1.x = *reinterpret_cast<unsigned*>(&h4);
            u1.y = *reinterpret_cast<unsigned*>(&h5);
            u1.z = *reinterpret_cast<unsigned*>(&h6);
            u1.w = *reinterpret_cast<unsigned*>(&h7);
            *reinterpret_cast<uint4*>(&Bs[wj][wkh + 0]) = u0;
            *reinterpret_cast<uint4*>(&Bs[wj][wkh + 8]) = u1;
        }
        // prefetch next W chunk (latency overlaps sync + MMA below)
        if (kc < 3) {
            const float4* wp = reinterpret_cast<const float4*>(
                &W[(size_t)wj * D + (kc + 1) * 32 + wkh]);
#pragma unroll
            for (int p = 0; p < 4; p++) wreg[p] = __ldg(wp + p);
        }
        __syncthreads();

#pragma unroll
        for (int s = 0; s < 2; s++) {
            int kg = kc * 32 + s * 16;      // global k for A
            int ks = s * 16;                // chunk-local k for B
            unsigned a0, a1, a2, a3;
            unsigned aaddr = smem_u32(&As[a_row][kg + a_koff]);
            asm volatile(
                "ldmatrix.sync.aligned.m8n8.x4.shared.b16 {%0,%1,%2,%3}, [%4];"
                : "=r"(a0), "=r"(a1), "=r"(a2), "=r"(a3) : "r"(aaddr));
#pragma unroll
            for (int p = 0; p < 8; p++) {
                unsigned b0, b1, b2, b3;
                unsigned baddr = smem_u32(&Bs[p * 16 + b_row2][ks + b_col2]);
                asm volatile(
                    "ldmatrix.sync.aligned.m8n8.x4.shared.b16 {%0,%1,%2,%3}, [%4];"
                    : "=r"(b0), "=r"(b1), "=r"(b2), "=r"(b3) : "r"(baddr));
                asm volatile(
                    "mma.sync.aligned.m16n8k16.row.col.f32.f16.f16.f32 "
                    "{%0,%1,%2,%3}, {%4,%5,%6,%7}, {%8,%9}, {%0,%1,%2,%3};"
                    : "+f"(acc[2 * p][0]), "+f"(acc[2 * p][1]),
                      "+f"(acc[2 * p][2]), "+f"(acc[2 * p][3])
                    : "r"(a0), "r"(a1), "r"(a2), "r"(a3), "r"(b0), "r"(b1));
                asm volatile(
                    "mma.sync.aligned.m16n8k16.row.col.f32.f16.f16.f32 "
                    "{%0,%1,%2,%3}, {%4,%5,%6,%7}, {%8,%9}, {%0,%1,%2,%3};"
                    : "+f"(acc[2 * p + 1][0]), "+f"(acc[2 * p + 1][1]),
                      "+f"(acc[2 * p + 1][2]), "+f"(acc[2 * p + 1][3])
                    : "r"(a0), "r"(a1), "r"(a2), "r"(a3), "r"(b2), "r"(b3));
            }
        }
    }

    // Epilogue: add bias, convert to fp16, store xl16.
    int gid = lane >> 2;     // C-fragment row group
    int tig = lane & 3;      // C-fragment col pair
    int row1 = row0 + m0 + gid;
    int row2 = row1 + 8;
#pragma unroll
    for (int nt = 0; nt < 16; nt++) {
        int col = nt * 8 + 2 * tig;
        float2 bv = *reinterpret_cast<const float2*>(&b[col]);
        if (row1 < N) {
            __half2 h = __float22half2_rn(
                make_float2(acc[nt][0] + bv.x, acc[nt][1] + bv.y));
            xl16[(size_t)row1 * (D / 2) + (col >> 1)] = h;
        }
        if (row2 < N) {
            __half2 h = __float22half2_rn(
                make_float2(acc[nt][2] + bv.x, acc[nt][3] + bv.y));
            xl16[(size_t)row2 * (D / 2) + (col >> 1)] = h;
        }
    }
}

// ---------------------------------------------------------------------------
// Fused CSR aggregation (fp16 gather, fp32 accumulate) + mean + residual + LN,
// then expmap (final) or analytic logmap∘expmap (identity when curvatures
// match). FULL warp per row. Dynamic 2-row chunks with a REDUCED grid
// (592 blocks = 4736 warps, ~5.3 chunks/warp) so the dynamic scheduler can
// actually balance — 1184 blocks gave 1.32 chunks/warp -> 2x makespan.
// ---------------------------------------------------------------------------
__global__ void k_aggfinal(const int* __restrict__ incl, const int* __restrict__ bsum,
                           const int* __restrict__ csr,
                           const __half2* __restrict__ xl16,
                           __half2* __restrict__ xt16,
                           const float* __restrict__ gamma, const float* __restrict__ beta,
                           const float* __restrict__ curv, int l,
                           float* __restrict__ out, int N, int final_) {
    int lane = threadIdx.x & 31;
    const uint2* xlu = reinterpret_cast<const uint2*>(xl16);   // 1 uint2 = 4 halves

    float c = clip_c(curv[l]);
    float K = 1.0f / c;
    float sqrtK = sqrtf(K);
    float cnext = final_ ? c : clip_c(curv[l + 1]);
    float4 g = reinterpret_cast<const float4*>(gamma)[lane];
    float4 bb = reinterpret_cast<const float4*>(beta)[lane];

    for (;;) {
        int base;
        if (lane == 0) base = (int)atomicAdd(&g_rowcur, 2u);
        base = __shfl_sync(0xFFFFFFFFu, base, 0);
        if (base >= N) return;
        int wend = base + 2 < N ? base + 2 : N;

        for (int w = base; w < wend; w++) {
            int beg = (w > 0) ? (incl[w - 1] + bsum[(w - 1) >> 8]) : 0;
            int end = incl[w] + bsum[w >> 8];
            float4 acc = make_float4(0.f, 0.f, 0.f, 0.f);

            int e = beg;
            for (; e + 8 <= end; e += 8) {
                int sidx[8];
#pragma unroll
                for (int t = 0; t < 8; t++) sidx[t] = __ldg(&csr[e + t]);
                uint2 q[8];
#pragma unroll
                for (int t = 0; t < 8; t++)
                    q[t] = __ldg(&xlu[(size_t)sidx[t] * 32 + lane]);
#pragma unroll
                for (int t = 0; t < 8; t++) {
                    float2 f0 = __half22float2(*reinterpret_cast<__half2*>(&q[t].x));
                    float2 f1 = __half22float2(*reinterpret_cast<__half2*>(&q[t].y));
                    acc.x += f0.x; acc.y += f0.y; acc.z += f1.x; acc.w += f1.y;
                }
            }
            if (e + 4 <= end) {
                int sidx[4];
#pragma unroll
                for (int t = 0; t < 4; t++) sidx[t] = __ldg(&csr[e + t]);
                uint2 q[4];
#pragma unroll
                for (int t = 0; t < 4; t++)
                    q[t] = __ldg(&xlu[(size_t)sidx[t] * 32 + lane]);
#pragma unroll
                for (int t = 0; t < 4; t++) {
                    float2 f0 = __half22float2(*reinterpret_cast<__half2*>(&q[t].x));
                    float2 f1 = __half22float2(*reinterpret_cast<__half2*>(&q[t].y));
                    acc.x += f0.x; acc.y += f0.y; acc.z += f1.x; acc.w += f1.y;
                }
                e += 4;
            }
            for (; e < end; e++) {
                int s = __ldg(&csr[e]);
                uint2 q = __ldg(&xlu[(size_t)s * 32 + lane]);
                float2 f0 = __half22float2(*reinterpret_cast<__half2*>(&q.x));
                float2 f1 = __half22float2(*reinterpret_cast<__half2*>(&q.y));
                acc.x += f0.x; acc.y += f0.y; acc.z += f1.x; acc.w += f1.y;
            }

            int dg = end - beg;
            float rcn = 1.0f / (float)(dg > 1 ? dg : 1);

            uint2 tu = __ldg(reinterpret_cast<const uint2*>(
                xt16 + (size_t)w * (D / 2)) + lane);
            float2 t0 = __half22float2(*reinterpret_cast<__half2*>(&tu.x));
            float2 t1 = __half22float2(*reinterpret_cast<__half2*>(&tu.y));
            float4 v = make_float4(t0.x + acc.x * rcn, t0.y + acc.y * rcn,
                                   t1.x + acc.z * rcn, t1.y + acc.w * rcn);

            float s1 = v.x + v.y + v.z + v.w;
            float s2 = v.x * v.x + v.y * v.y + v.z * v.z + v.w * v.w;
            s1 = warp_sum(s1);
            s2 = warp_sum(s2);
            float mean = s1 * (1.0f / D);
            float var = s2 * (1.0f / D) - mean * mean;
            float rstd = rsqrtf(var + 1e-5f);

            float4 y = make_float4((v.x - mean) * rstd * g.x + bb.x,
                                   (v.y - mean) * rstd * g.y + bb.y,
                                   (v.z - mean) * rstd * g.z + bb.z,
                                   (v.w - mean) * rstd * g.w + bb.w);

            float ss = y.x * y.x + y.y * y.y + y.z * y.z + y.w * y.w;
            ss = warp_sum(ss);
            float r = sqrtf(ss);

            if (final_) {
                float sc = sqrtK * sinhf(r / sqrtK) / fmaxf(r, 1e-7f);
                float4 o = make_float4(y.x * sc, y.y * sc, y.z * sc, y.w * sc);
                reinterpret_cast<float4*>(out + (size_t)w * D)[lane] = o;
            } else {
                float sc;
                if (c == cnext) {
                    sc = 1.0f;   // logmap_c(expmap_c(y)) == y exactly
                } else {
                    float se = sqrtK * sinhf(r / sqrtK) / fmaxf(r, 1e-7f);
                    float un = se * r;
                    float K1 = 1.0f / cnext;
                    float sk1 = sqrtf(K1);
                    float t = sqrtf(K1 + un * un);
                    float theta = acoshf(fmaxf(t / sk1, 1.0f + 1e-7f));
                    sc = se * sk1 * theta / fmaxf(un, 1e-7f);
                }
                __half2 h0 = __float22half2_rn(make_float2(y.x * sc, y.y * sc));
                __half2 h1 = __float22half2_rn(make_float2(y.z * sc, y.w * sc));
                uint2 u;
                u.x = *reinterpret_cast<unsigned*>(&h0);
                u.y = *reinterpret_cast<unsigned*>(&h1);
                *reinterpret_cast<uint2*>(xt16 + (size_t)w * (D / 2) + lane * 2) = u;
            }
        }
    }
}

// ---------------------------------------------------------------------------
extern "C" void kernel_launch(void* const* d_in, const int* in_sizes, int n_in,
                              void* d_out, int out_size) {
    const float* x_hyp      = (const float*)d_in[0];
    const void*  ei         = d_in[1];
    const float* W          = (const float*)d_in[2];
    const float* b          = (const float*)d_in[3];
    const float* gamma      = (const float*)d_in[4];
    const float* beta       = (const float*)d_in[5];
    const float* curv       = (const float*)d_in[6];

    int N = in_sizes[0] / D;
    int E = in_sizes[1] / 2;
    int L = in_sizes[6];

    __half2 *xl16, *xt16;
    int *deg, *cursor, *incl, *bsum, *csr;
    cudaGetSymbolAddress((void**)&xt16, g_xt16);
    cudaGetSymbolAddress((void**)&xl16, g_xl16);
    cudaGetSymbolAddress((void**)&deg,  g_deg);
    cudaGetSymbolAddress((void**)&cursor, g_cursor);
    cudaGetSymbolAddress((void**)&incl, g_incl);
    cudaGetSymbolAddress((void**)&bsum, g_bsum);
    cudaGetSymbolAddress((void**)&csr,  g_csr);

    int nb = (N + 255) / 256;

    // One-time CSR build: 3 launches (scanB fused into scanA last-block).
    k_hist<<<(E + 255) / 256, 256>>>(ei, deg, E, N);
    k_scanA<<<nb, 256>>>(deg, incl, bsum, cursor, N, nb);
    k_fill<<<(E + 255) / 256, 256>>>(ei, incl, bsum, cursor, csr, E, N);

    for (int l = 0; l < L; l++) {
        k_gemm_fused<<<(N + 127) / 128, 256>>>(x_hyp, W + (size_t)l * D * D,
                                               b + (size_t)l * D, xt16, xl16,
                                               curv, l, N, l == 0 ? 1 : 0);
        int fin = (l == L - 1) ? 1 : 0;
        k_aggfinal<<<592, 256>>>(incl, bsum, csr, xl16, xt16,
                                 gamma + (size_t)l * D, beta + (size_t)l * D,
                                 curv, l, (float*)d_out, N, fin);
    }
}

// round 15
// speedup vs baseline: 1.1195x; 1.1195x over previous
#include <cuda_runtime.h>
#include <cuda_fp16.h>
#include <math.h>

#define D 128
#define MAXN 65536
#define MAXE 1100000

// Scratch (allocation-free rule: __device__ globals)
__device__ __half2  g_xt16[MAXN * (D / 2)];
__device__ __half2  g_xl16[MAXN * (D / 2)];
__device__ int      g_deg[MAXN];
__device__ int      g_cursor[MAXN];
__device__ int      g_incl[MAXN];
__device__ int      g_bsum[512];
__device__ int      g_csr[MAXE];
__device__ unsigned g_rowcur;
__device__ unsigned g_done;

__device__ __forceinline__ float warp_sum(float v) {
#pragma unroll
    for (int o = 16; o; o >>= 1) v += __shfl_xor_sync(0xFFFFFFFFu, v, o);
    return v;
}

__device__ __forceinline__ float clip_c(float c) {
    return fminf(fmaxf(c, 0.1f), 10.0f);
}

__device__ __forceinline__ unsigned smem_u32(const void* p) {
    return (unsigned)__cvta_generic_to_shared(p);
}

// Per-block edge-index dtype detection: read first 64 int64 words; if any is
// outside [0,N) the buffer is int32 (misdetect needs 64 consecutive zero
// high-words: p=(1/N)^64 ~ 0). Returns 1 if int64.
__device__ __forceinline__ int detect_is64(const void* ei, int E, long long N) {
    const long long* p64 = (const long long*)ei;
    int n = 2 * E < 128 ? E : 64;
    int bad = 0;
    for (int i = threadIdx.x; i < n; i += 256) {
        long long v = p64[i];
        if (v < 0 || v >= N) bad = 1;
    }
    return !__syncthreads_or(bad);
}

// ---------------------------------------------------------------------------
// In-degree histogram straight from ei (inline dtype detection).
// deg/cursor are pre-zeroed by the PREVIOUS execution's k_scanA (static-init
// zero on the first execution) -> deterministic every replay.
// ---------------------------------------------------------------------------
__global__ void k_hist(const void* __restrict__ ei, int* __restrict__ deg,
                       int E, int N) {
    int is64 = detect_is64(ei, E, (long long)N);
    int e = blockIdx.x * blockDim.x + threadIdx.x;
    if (e >= E) return;
    long long d;
    if (is64) d = ((const long long*)ei)[(size_t)E + e];
    else      d = (long long)((const int*)ei)[(size_t)E + e];
    int di = (int)min(max(d, 0LL), (long long)(N - 1));
    atomicAdd(&deg[di], 1);
}

// ---------------------------------------------------------------------------
// Prefix scan with fused block-sum scan (last-block pattern): per-block
// inclusive scan into incl + block sums into bsum; the LAST block to finish
// scans bsum in place (exclusive) and resets the done counter.
// scanA also re-zeroes deg and cursor so no memset pass.
// rowstart reconstructed by readers: rowstart[g+1] = incl[g] + bsum[g>>8].
// ---------------------------------------------------------------------------
__global__ void k_scanA(int* __restrict__ deg, int* __restrict__ incl,
                        int* __restrict__ bsum, int* __restrict__ cursor,
                        int N, int nb) {
    __shared__ int wsum[8];
    __shared__ bool isLast;
    int tid = threadIdx.x, lane = tid & 31, warp = tid >> 5;
    int gid = blockIdx.x * 256 + tid;
    int v = (gid < N) ? deg[gid] : 0;
    int x = v;
#pragma unroll
    for (int o = 1; o < 32; o <<= 1) {
        int y = __shfl_up_sync(0xFFFFFFFFu, x, o);
        if (lane >= o) x += y;
    }
    if (lane == 31) wsum[warp] = x;
    __syncthreads();
    if (warp == 0) {
        int s = (lane < 8) ? wsum[lane] : 0;
        int y = s;
#pragma unroll
        for (int o = 1; o < 8; o <<= 1) {
            int z = __shfl_up_sync(0xFFFFFFFFu, y, o);
            if (lane >= o) y += z;
        }
        if (lane < 8) wsum[lane] = y - s;   // exclusive warp offset
    }
    __syncthreads();
    int inclv = x + wsum[warp];
    if (gid < N) {
        incl[gid] = inclv;
        deg[gid] = 0;      // pre-zero for next execution's k_hist
        cursor[gid] = 0;   // pre-zero for this execution's k_fill
    }
    if (tid == 255) bsum[blockIdx.x] = inclv;

    // --- last-block tail: scan bsum[0..nb) exclusive, in place ---
    __threadfence();
    if (tid == 0) {
        unsigned prev = atomicAdd(&g_done, 1u);
        isLast = (prev == (unsigned)(gridDim.x - 1));
    }
    __syncthreads();
    if (!isLast) return;
    if (tid == 0) g_done = 0u;   // reset for next replay (deterministic)

    int bv = (tid < nb) ? bsum[tid] : 0;
    int bx = bv;
#pragma unroll
    for (int o = 1; o < 32; o <<= 1) {
        int y = __shfl_up_sync(0xFFFFFFFFu, bx, o);
        if (lane >= o) bx += y;
    }
    __syncthreads();   // reuse wsum
    if (lane == 31) wsum[warp] = bx;
    __syncthreads();
    if (warp == 0) {
        int s = (lane < 8) ? wsum[lane] : 0;
        int y = s;
#pragma unroll
        for (int o = 1; o < 8; o <<= 1) {
            int z = __shfl_up_sync(0xFFFFFFFFu, y, o);
            if (lane >= o) y += z;
        }
        if (lane < 8) wsum[lane] = y - s;
    }
    __syncthreads();
    if (tid < nb) bsum[tid] = bx + wsum[warp] - bv;   // exclusive block offset
}

// ---------------------------------------------------------------------------
// CSR fill straight from ei (inline dtype detection, clamped), rowstart inline.
// ---------------------------------------------------------------------------
__global__ void k_fill(const void* __restrict__ ei,
                       const int* __restrict__ incl, const int* __restrict__ bsum,
                       int* __restrict__ cursor, int* __restrict__ csr,
                       int E, int N) {
    int is64 = detect_is64(ei, E, (long long)N);
    int e = blockIdx.x * blockDim.x + threadIdx.x;
    if (e >= E) return;
    long long s, d;
    if (is64) {
        const long long* p = (const long long*)ei;
        s = p[e];
        d = p[(size_t)E + e];
    } else {
        const int* p = (const int*)ei;
        s = p[e];
        d = p[(size_t)E + e];
    }
    int si = (int)min(max(s, 0LL), (long long)(N - 1));
    int di = (int)min(max(d, 0LL), (long long)(N - 1));
    int rs = (di > 0) ? (incl[di - 1] + bsum[(di - 1) >> 8]) : 0;
    int pos = rs + atomicAdd(&cursor[di], 1);
    csr[pos] = si;
}

// ---------------------------------------------------------------------------
// Fused (logmap+) HMMA GEMM.
// first=1: load fp32 x_hyp, apply logmap (4-row interleaved batches for ILP),
//          write xt16 + As.
// first=0: load fp16 xt16 (already the tangent vector) straight into As.
// Block: 128 rows x 128 cols, 8 warps; Bs pitch 40 halves (conflict-free);
// W register-prefetch; B fragments via ldmatrix.x4.
// Block 0 thread 0 also resets the agg row cursor.
// ---------------------------------------------------------------------------
__global__ void __launch_bounds__(256) k_gemm_fused(
        const float* __restrict__ xin, const float* __restrict__ W,
        const float* __restrict__ b, __half2* __restrict__ xt16,
        __half2* __restrict__ xl16, const float* __restrict__ curv,
        int l, int N, int first) {
    __shared__ __half As[128][136];   // 34816 B
    __shared__ __half Bs[128][40];    // 10240 B  (total 44 KB)
    int tid = threadIdx.x;
    int lane = tid & 31;
    int wid = tid >> 5;
    int row0 = blockIdx.x * 128;
    int m0 = wid * 16;

    if (blockIdx.x == 0 && tid == 0) g_rowcur = 0u;   // reset agg cursor

    if (first) {
        float c = clip_c(curv[l]);
        float K = 1.0f / c;
        float sqrtK = sqrtf(K);
#pragma unroll
        for (int bt = 0; bt < 4; bt++) {
            float4 v[4];
            float ss[4];
#pragma unroll
            for (int j = 0; j < 4; j++) {
                int grow = row0 + m0 + bt * 4 + j;
                v[j] = make_float4(0.f, 0.f, 0.f, 0.f);
                if (grow < N)
                    v[j] = __ldg(reinterpret_cast<const float4*>(
                        xin + (size_t)grow * D) + lane);
            }
#pragma unroll
            for (int j = 0; j < 4; j++)
                ss[j] = v[j].x * v[j].x + v[j].y * v[j].y +
                        v[j].z * v[j].z + v[j].w * v[j].w;
            // interleaved warp reductions: 4 independent shfl chains
#pragma unroll
            for (int o = 16; o; o >>= 1) {
#pragma unroll
                for (int j = 0; j < 4; j++)
                    ss[j] += __shfl_xor_sync(0xFFFFFFFFu, ss[j], o);
            }
#pragma unroll
            for (int j = 0; j < 4; j++) {
                int row = m0 + bt * 4 + j;
                int grow = row0 + row;
                float xnorm = sqrtf(ss[j]);
                float t = sqrtf(K + ss[j]);
                float theta = acoshf(fmaxf(t / sqrtK, 1.0f + 1e-7f));
                float s = sqrtK * theta / fmaxf(xnorm, 1e-7f);
                float4 u4 = make_float4(v[j].x * s, v[j].y * s,
                                        v[j].z * s, v[j].w * s);
                __half2 h0 = __float22half2_rn(make_float2(u4.x, u4.y));
                __half2 h1 = __float22half2_rn(make_float2(u4.z, u4.w));
                uint2 u;
                u.x = *reinterpret_cast<unsigned*>(&h0);
                u.y = *reinterpret_cast<unsigned*>(&h1);
                if (grow < N)
                    *reinterpret_cast<uint2*>(
                        xt16 + (size_t)grow * (D / 2) + lane * 2) = u;
                *reinterpret_cast<uint2*>(&As[row][lane * 4]) = u;
            }
        }
    } else {
#pragma unroll
        for (int i = 0; i < 16; i++) {
            int row = m0 + i;
            int grow = row0 + row;
            uint2 u = make_uint2(0u, 0u);
            if (grow < N)
                u = __ldg(reinterpret_cast<const uint2*>(
                    xt16 + (size_t)grow * (D / 2)) + lane);
            *reinterpret_cast<uint2*>(&As[row][lane * 4]) = u;
        }
    }

    float acc[16][4];
#pragma unroll
    for (int nt = 0; nt < 16; nt++)
#pragma unroll
        for (int q = 0; q < 4; q++) acc[nt][q] = 0.0f;

    // ldmatrix lane address components
    int a_rr = lane & 7;
    int a_sel = lane >> 3;                  // 0..3
    int a_row = m0 + a_rr + ((a_sel & 1) ? 8 : 0);
    int a_koff = (a_sel >> 1) ? 8 : 0;
    int b_row2 = (lane & 7) + ((lane & 16) ? 8 : 0);
    int b_col2 = (lane & 8) ? 8 : 0;

    // W staging assignment: thread -> row j, k-half
    int wj = tid >> 1;
    int wkh = (tid & 1) * 16;

    // prefetch W chunk 0 into registers
    float4 wreg[4];
    {
        const float4* wp = reinterpret_cast<const float4*>(&W[(size_t)wj * D + wkh]);
#pragma unroll
        for (int p = 0; p < 4; p++) wreg[p] = __ldg(wp + p);
    }

    for (int kc = 0; kc < 4; kc++) {
        __syncthreads();   // previous Bs consumed; kc=0 also covers As writes
        // store registered W chunk to Bs (fp16)
        {
            __half2 h0 = __float22half2_rn(make_float2(wreg[0].x, wreg[0].y));
            __half2 h1 = __float22half2_rn(make_float2(wreg[0].z, wreg[0].w));
            __half2 h2 = __float22half2_rn(make_float2(wreg[1].x, wreg[1].y));
            __half2 h3 = __float22half2_rn(make_float2(wreg[1].z, wreg[1].w));
            __half2 h4 = __float22half2_rn(make_float2(wreg[2].x, wreg[2].y));
            __half2 h5 = __float22half2_rn(make_float2(wreg[2].z, wreg[2].w));
            __half2 h6 = __float22half2_rn(make_float2(wreg[3].x, wreg[3].y));
            __half2 h7 = __float22half2_rn(make_float2(wreg[3].z, wreg[3].w));
            uint4 u0, u1;
            u0.x = *reinterpret_cast<unsigned*>(&h0);
            u0.y = *reinterpret_cast<unsigned*>(&h1);
            u0.z = *reinterpret_cast<unsigned*>(&h2);
            u0.w = *reinterpret_cast<unsigned*>(&h3);
            u1.x = *reinterpret_cast<unsigned*>(&h4);
            u1.y = *reinterpret_cast<unsigned*>(&h5);
            u1.z = *reinterpret_cast<unsigned*>(&h6);
            u1.w = *reinterpret_cast<unsigned*>(&h7);
            *reinterpret_cast<uint4*>(&Bs[wj][wkh + 0]) = u0;
            *reinterpret_cast<uint4*>(&Bs[wj][wkh + 8]) = u1;
        }
        // prefetch next W chunk (latency overlaps sync + MMA below)
        if (kc < 3) {
            const float4* wp = reinterpret_cast<const float4*>(
                &W[(size_t)wj * D + (kc + 1) * 32 + wkh]);
#pragma unroll
            for (int p = 0; p < 4; p++) wreg[p] = __ldg(wp + p);
        }
        __syncthreads();

#pragma unroll
        for (int s = 0; s < 2; s++) {
            int kg = kc * 32 + s * 16;      // global k for A
            int ks = s * 16;                // chunk-local k for B
            unsigned a0, a1, a2, a3;
            unsigned aaddr = smem_u32(&As[a_row][kg + a_koff]);
            asm volatile(
                "ldmatrix.sync.aligned.m8n8.x4.shared.b16 {%0,%1,%2,%3}, [%4];"
                : "=r"(a0), "=r"(a1), "=r"(a2), "=r"(a3) : "r"(aaddr));
#pragma unroll
            for (int p = 0; p < 8; p++) {
                unsigned b0, b1, b2, b3;
                unsigned baddr = smem_u32(&Bs[p * 16 + b_row2][ks + b_col2]);
                asm volatile(
                    "ldmatrix.sync.aligned.m8n8.x4.shared.b16 {%0,%1,%2,%3}, [%4];"
                    : "=r"(b0), "=r"(b1), "=r"(b2), "=r"(b3) : "r"(baddr));
                asm volatile(
                    "mma.sync.aligned.m16n8k16.row.col.f32.f16.f16.f32 "
                    "{%0,%1,%2,%3}, {%4,%5,%6,%7}, {%8,%9}, {%0,%1,%2,%3};"
                    : "+f"(acc[2 * p][0]), "+f"(acc[2 * p][1]),
                      "+f"(acc[2 * p][2]), "+f"(acc[2 * p][3])
                    : "r"(a0), "r"(a1), "r"(a2), "r"(a3), "r"(b0), "r"(b1));
                asm volatile(
                    "mma.sync.aligned.m16n8k16.row.col.f32.f16.f16.f32 "
                    "{%0,%1,%2,%3}, {%4,%5,%6,%7}, {%8,%9}, {%0,%1,%2,%3};"
                    : "+f"(acc[2 * p + 1][0]), "+f"(acc[2 * p + 1][1]),
                      "+f"(acc[2 * p + 1][2]), "+f"(acc[2 * p + 1][3])
                    : "r"(a0), "r"(a1), "r"(a2), "r"(a3), "r"(b2), "r"(b3));
            }
        }
    }

    // Epilogue: add bias, convert to fp16, store xl16.
    int gid = lane >> 2;     // C-fragment row group
    int tig = lane & 3;      // C-fragment col pair
    int row1 = row0 + m0 + gid;
    int row2 = row1 + 8;
#pragma unroll
    for (int nt = 0; nt < 16; nt++) {
        int col = nt * 8 + 2 * tig;
        float2 bv = *reinterpret_cast<const float2*>(&b[col]);
        if (row1 < N) {
            __half2 h = __float22half2_rn(
                make_float2(acc[nt][0] + bv.x, acc[nt][1] + bv.y));
            xl16[(size_t)row1 * (D / 2) + (col >> 1)] = h;
        }
        if (row2 < N) {
            __half2 h = __float22half2_rn(
                make_float2(acc[nt][2] + bv.x, acc[nt][3] + bv.y));
            xl16[(size_t)row2 * (D / 2) + (col >> 1)] = h;
        }
    }
}

// ---------------------------------------------------------------------------
// Fused CSR aggregation (fp16 gather, fp32 accumulate) + mean + residual + LN,
// then expmap (final) or analytic logmap∘expmap (identity when curvatures
// match). FULL warp per row. Dynamic 2-row chunks at FULL grid (1184 blocks:
// max resident warps — R14 showed agg is parallelism-hungry; chunk 2 gives
// 2.6 chunks/warp for balance without losing warps).
// ---------------------------------------------------------------------------
__global__ void k_aggfinal(const int* __restrict__ incl, const int* __restrict__ bsum,
                           const int* __restrict__ csr,
                           const __half2* __restrict__ xl16,
                           __half2* __restrict__ xt16,
                           const float* __restrict__ gamma, const float* __restrict__ beta,
                           const float* __restrict__ curv, int l,
                           float* __restrict__ out, int N, int final_) {
    int lane = threadIdx.x & 31;
    const uint2* xlu = reinterpret_cast<const uint2*>(xl16);   // 1 uint2 = 4 halves

    float c = clip_c(curv[l]);
    float K = 1.0f / c;
    float sqrtK = sqrtf(K);
    float cnext = final_ ? c : clip_c(curv[l + 1]);
    float4 g = reinterpret_cast<const float4*>(gamma)[lane];
    float4 bb = reinterpret_cast<const float4*>(beta)[lane];

    for (;;) {
        int base;
        if (lane == 0) base = (int)atomicAdd(&g_rowcur, 2u);
        base = __shfl_sync(0xFFFFFFFFu, base, 0);
        if (base >= N) return;
        int wend = base + 2 < N ? base + 2 : N;

        for (int w = base; w < wend; w++) {
            int beg = (w > 0) ? (incl[w - 1] + bsum[(w - 1) >> 8]) : 0;
            int end = incl[w] + bsum[w >> 8];
            float4 acc = make_float4(0.f, 0.f, 0.f, 0.f);

            int e = beg;
            for (; e + 8 <= end; e += 8) {
                int sidx[8];
#pragma unroll
                for (int t = 0; t < 8; t++) sidx[t] = __ldg(&csr[e + t]);
                uint2 q[8];
#pragma unroll
                for (int t = 0; t < 8; t++)
                    q[t] = __ldg(&xlu[(size_t)sidx[t] * 32 + lane]);
#pragma unroll
                for (int t = 0; t < 8; t++) {
                    float2 f0 = __half22float2(*reinterpret_cast<__half2*>(&q[t].x));
                    float2 f1 = __half22float2(*reinterpret_cast<__half2*>(&q[t].y));
                    acc.x += f0.x; acc.y += f0.y; acc.z += f1.x; acc.w += f1.y;
                }
            }
            if (e + 4 <= end) {
                int sidx[4];
#pragma unroll
                for (int t = 0; t < 4; t++) sidx[t] = __ldg(&csr[e + t]);
                uint2 q[4];
#pragma unroll
                for (int t = 0; t < 4; t++)
                    q[t] = __ldg(&xlu[(size_t)sidx[t] * 32 + lane]);
#pragma unroll
                for (int t = 0; t < 4; t++) {
                    float2 f0 = __half22float2(*reinterpret_cast<__half2*>(&q[t].x));
                    float2 f1 = __half22float2(*reinterpret_cast<__half2*>(&q[t].y));
                    acc.x += f0.x; acc.y += f0.y; acc.z += f1.x; acc.w += f1.y;
                }
                e += 4;
            }
            for (; e < end; e++) {
                int s = __ldg(&csr[e]);
                uint2 q = __ldg(&xlu[(size_t)s * 32 + lane]);
                float2 f0 = __half22float2(*reinterpret_cast<__half2*>(&q.x));
                float2 f1 = __half22float2(*reinterpret_cast<__half2*>(&q.y));
                acc.x += f0.x; acc.y += f0.y; acc.z += f1.x; acc.w += f1.y;
            }

            int dg = end - beg;
            float rcn = 1.0f / (float)(dg > 1 ? dg : 1);

            uint2 tu = __ldg(reinterpret_cast<const uint2*>(
                xt16 + (size_t)w * (D / 2)) + lane);
            float2 t0 = __half22float2(*reinterpret_cast<__half2*>(&tu.x));
            float2 t1 = __half22float2(*reinterpret_cast<__half2*>(&tu.y));
            float4 v = make_float4(t0.x + acc.x * rcn, t0.y + acc.y * rcn,
                                   t1.x + acc.z * rcn, t1.y + acc.w * rcn);

            float s1 = v.x + v.y + v.z + v.w;
            float s2 = v.x * v.x + v.y * v.y + v.z * v.z + v.w * v.w;
            s1 = warp_sum(s1);
            s2 = warp_sum(s2);
            float mean = s1 * (1.0f / D);
            float var = s2 * (1.0f / D) - mean * mean;
            float rstd = rsqrtf(var + 1e-5f);

            float4 y = make_float4((v.x - mean) * rstd * g.x + bb.x,
                                   (v.y - mean) * rstd * g.y + bb.y,
                                   (v.z - mean) * rstd * g.z + bb.z,
                                   (v.w - mean) * rstd * g.w + bb.w);

            float ss = y.x * y.x + y.y * y.y + y.z * y.z + y.w * y.w;
            ss = warp_sum(ss);
            float r = sqrtf(ss);

            if (final_) {
                float sc = sqrtK * sinhf(r / sqrtK) / fmaxf(r, 1e-7f);
                float4 o = make_float4(y.x * sc, y.y * sc, y.z * sc, y.w * sc);
                reinterpret_cast<float4*>(out + (size_t)w * D)[lane] = o;
            } else {
                float sc;
                if (c == cnext) {
                    sc = 1.0f;   // logmap_c(expmap_c(y)) == y exactly
                } else {
                    float se = sqrtK * sinhf(r / sqrtK) / fmaxf(r, 1e-7f);
                    float un = se * r;
                    float K1 = 1.0f / cnext;
                    float sk1 = sqrtf(K1);
                    float t = sqrtf(K1 + un * un);
                    float theta = acoshf(fmaxf(t / sk1, 1.0f + 1e-7f));
                    sc = se * sk1 * theta / fmaxf(un, 1e-7f);
                }
                __half2 h0 = __float22half2_rn(make_float2(y.x * sc, y.y * sc));
                __half2 h1 = __float22half2_rn(make_float2(y.z * sc, y.w * sc));
                uint2 u;
                u.x = *reinterpret_cast<unsigned*>(&h0);
                u.y = *reinterpret_cast<unsigned*>(&h1);
                *reinterpret_cast<uint2*>(xt16 + (size_t)w * (D / 2) + lane * 2) = u;
            }
        }
    }
}

// ---------------------------------------------------------------------------
extern "C" void kernel_launch(void* const* d_in, const int* in_sizes, int n_in,
                              void* d_out, int out_size) {
    const float* x_hyp      = (const float*)d_in[0];
    const void*  ei         = d_in[1];
    const float* W          = (const float*)d_in[2];
    const float* b          = (const float*)d_in[3];
    const float* gamma      = (const float*)d_in[4];
    const float* beta       = (const float*)d_in[5];
    const float* curv       = (const float*)d_in[6];

    int N = in_sizes[0] / D;
    int E = in_sizes[1] / 2;
    int L = in_sizes[6];

    __half2 *xl16, *xt16;
    int *deg, *cursor, *incl, *bsum, *csr;
    cudaGetSymbolAddress((void**)&xt16, g_xt16);
    cudaGetSymbolAddress((void**)&xl16, g_xl16);
    cudaGetSymbolAddress((void**)&deg,  g_deg);
    cudaGetSymbolAddress((void**)&cursor, g_cursor);
    cudaGetSymbolAddress((void**)&incl, g_incl);
    cudaGetSymbolAddress((void**)&bsum, g_bsum);
    cudaGetSymbolAddress((void**)&csr,  g_csr);

    int nb = (N + 255) / 256;

    // One-time CSR build: 3 launches (scanB fused into scanA last-block).
    k_hist<<<(E + 255) / 256, 256>>>(ei, deg, E, N);
    k_scanA<<<nb, 256>>>(deg, incl, bsum, cursor, N, nb);
    k_fill<<<(E + 255) / 256, 256>>>(ei, incl, bsum, cursor, csr, E, N);

    for (int l = 0; l < L; l++) {
        k_gemm_fused<<<(N + 127) / 128, 256>>>(x_hyp, W + (size_t)l * D * D,
                                               b + (size_t)l * D, xt16, xl16,
                                               curv, l, N, l == 0 ? 1 : 0);
        int fin = (l == L - 1) ? 1 : 0;
        k_aggfinal<<<1184, 256>>>(incl, bsum, csr, xl16, xt16,
                                  gamma + (size_t)l * D, beta + (size_t)l * D,
                                  curv, l, (float*)d_out, N, fin);
    }
}

// round 16
// speedup vs baseline: 1.1452x; 1.0229x over previous
#include <cuda_runtime.h>
#include <cuda_fp16.h>
#include <math.h>

#define D 128
#define MAXN 65536
#define MAXE 1100000

// Scratch (allocation-free rule: __device__ globals)
__device__ __half2  g_xt16[MAXN * (D / 2)];
__device__ __half2  g_xl16[MAXN * (D / 2)];
__device__ int      g_deg[MAXN];
__device__ int      g_cursor[MAXN];
__device__ int      g_incl[MAXN];
__device__ int      g_bsum[512];
__device__ int      g_csr[MAXE];
__device__ unsigned g_rowcur;
__device__ unsigned g_done;

__device__ __forceinline__ float warp_sum(float v) {
#pragma unroll
    for (int o = 16; o; o >>= 1) v += __shfl_xor_sync(0xFFFFFFFFu, v, o);
    return v;
}

__device__ __forceinline__ float clip_c(float c) {
    return fminf(fmaxf(c, 0.1f), 10.0f);
}

__device__ __forceinline__ unsigned smem_u32(const void* p) {
    return (unsigned)__cvta_generic_to_shared(p);
}

// Per-block edge-index dtype detection: read first 64 int64 words; if any is
// outside [0,N) the buffer is int32 (misdetect needs 64 consecutive zero
// high-words: p=(1/N)^64 ~ 0). Returns 1 if int64.
__device__ __forceinline__ int detect_is64(const void* ei, int E, long long N) {
    const long long* p64 = (const long long*)ei;
    int n = 2 * E < 128 ? E : 64;
    int bad = 0;
    for (int i = threadIdx.x; i < n; i += 256) {
        long long v = p64[i];
        if (v < 0 || v >= N) bad = 1;
    }
    return !__syncthreads_or(bad);
}

// ---------------------------------------------------------------------------
// In-degree histogram straight from ei (inline dtype detection).
// deg/cursor are pre-zeroed by the PREVIOUS execution's k_scanA (static-init
// zero on the first execution) -> deterministic every replay.
// ---------------------------------------------------------------------------
__global__ void k_hist(const void* __restrict__ ei, int* __restrict__ deg,
                       int E, int N) {
    int is64 = detect_is64(ei, E, (long long)N);
    int e = blockIdx.x * blockDim.x + threadIdx.x;
    if (e >= E) return;
    long long d;
    if (is64) d = ((const long long*)ei)[(size_t)E + e];
    else      d = (long long)((const int*)ei)[(size_t)E + e];
    int di = (int)min(max(d, 0LL), (long long)(N - 1));
    atomicAdd(&deg[di], 1);
}

// ---------------------------------------------------------------------------
// Prefix scan with fused block-sum scan (last-block pattern): per-block
// inclusive scan into incl + block sums into bsum; the LAST block to finish
// scans bsum in place (exclusive) and resets the done counter.
// scanA also re-zeroes deg and cursor so no memset pass.
// rowstart reconstructed by readers: rowstart[g+1] = incl[g] + bsum[g>>8].
// ---------------------------------------------------------------------------
__global__ void k_scanA(int* __restrict__ deg, int* __restrict__ incl,
                        int* __restrict__ bsum, int* __restrict__ cursor,
                        int N, int nb) {
    __shared__ int wsum[8];
    __shared__ bool isLast;
    int tid = threadIdx.x, lane = tid & 31, warp = tid >> 5;
    int gid = blockIdx.x * 256 + tid;
    int v = (gid < N) ? deg[gid] : 0;
    int x = v;
#pragma unroll
    for (int o = 1; o < 32; o <<= 1) {
        int y = __shfl_up_sync(0xFFFFFFFFu, x, o);
        if (lane >= o) x += y;
    }
    if (lane == 31) wsum[warp] = x;
    __syncthreads();
    if (warp == 0) {
        int s = (lane < 8) ? wsum[lane] : 0;
        int y = s;
#pragma unroll
        for (int o = 1; o < 8; o <<= 1) {
            int z = __shfl_up_sync(0xFFFFFFFFu, y, o);
            if (lane >= o) y += z;
        }
        if (lane < 8) wsum[lane] = y - s;   // exclusive warp offset
    }
    __syncthreads();
    int inclv = x + wsum[warp];
    if (gid < N) {
        incl[gid] = inclv;
        deg[gid] = 0;      // pre-zero for next execution's k_hist
        cursor[gid] = 0;   // pre-zero for this execution's k_fill
    }
    if (tid == 255) bsum[blockIdx.x] = inclv;

    // --- last-block tail: scan bsum[0..nb) exclusive, in place ---
    __threadfence();
    if (tid == 0) {
        unsigned prev = atomicAdd(&g_done, 1u);
        isLast = (prev == (unsigned)(gridDim.x - 1));
    }
    __syncthreads();
    if (!isLast) return;
    if (tid == 0) g_done = 0u;   // reset for next replay (deterministic)

    int bv = (tid < nb) ? bsum[tid] : 0;
    int bx = bv;
#pragma unroll
    for (int o = 1; o < 32; o <<= 1) {
        int y = __shfl_up_sync(0xFFFFFFFFu, bx, o);
        if (lane >= o) bx += y;
    }
    __syncthreads();   // reuse wsum
    if (lane == 31) wsum[warp] = bx;
    __syncthreads();
    if (warp == 0) {
        int s = (lane < 8) ? wsum[lane] : 0;
        int y = s;
#pragma unroll
        for (int o = 1; o < 8; o <<= 1) {
            int z = __shfl_up_sync(0xFFFFFFFFu, y, o);
            if (lane >= o) y += z;
        }
        if (lane < 8) wsum[lane] = y - s;
    }
    __syncthreads();
    if (tid < nb) bsum[tid] = bx + wsum[warp] - bv;   // exclusive block offset
}

// ---------------------------------------------------------------------------
// CSR fill straight from ei (inline dtype detection, clamped), rowstart inline.
// ---------------------------------------------------------------------------
__global__ void k_fill(const void* __restrict__ ei,
                       const int* __restrict__ incl, const int* __restrict__ bsum,
                       int* __restrict__ cursor, int* __restrict__ csr,
                       int E, int N) {
    int is64 = detect_is64(ei, E, (long long)N);
    int e = blockIdx.x * blockDim.x + threadIdx.x;
    if (e >= E) return;
    long long s, d;
    if (is64) {
        const long long* p = (const long long*)ei;
        s = p[e];
        d = p[(size_t)E + e];
    } else {
        const int* p = (const int*)ei;
        s = p[e];
        d = p[(size_t)E + e];
    }
    int si = (int)min(max(s, 0LL), (long long)(N - 1));
    int di = (int)min(max(d, 0LL), (long long)(N - 1));
    int rs = (di > 0) ? (incl[di - 1] + bsum[(di - 1) >> 8]) : 0;
    int pos = rs + atomicAdd(&cursor[di], 1);
    csr[pos] = si;
}

// ---------------------------------------------------------------------------
// Fused (logmap+) HMMA GEMM, COLUMN-SPLIT tiles for occupancy:
// block = 128 rows x 64 cols (bx>>1 = row tile, bx&1 = col half).
// Each warp: 16 rows x 64 cols -> 8 n-tiles = 32 accumulators -> ~70 regs
// -> 3 CTAs/SM (was 102 regs / 2 CTAs / 1.32 waves = 34% tail waste).
// first=1: fp32 x_hyp + logmap (4-row ILP batches), write xt16 + As.
// first=0: fp16 xt16 straight into As. Bs 64x40 halves (pitch-5 c-free).
// Block 0 thread 0 resets the agg row cursor.
// ---------------------------------------------------------------------------
__global__ void __launch_bounds__(256, 3) k_gemm_fused(
        const float* __restrict__ xin, const float* __restrict__ W,
        const float* __restrict__ b, __half2* __restrict__ xt16,
        __half2* __restrict__ xl16, const float* __restrict__ curv,
        int l, int N, int first) {
    __shared__ __half As[128][136];   // 34816 B
    __shared__ __half Bs[64][40];     //  5120 B  (total ~39 KB)
    int tid = threadIdx.x;
    int lane = tid & 31;
    int wid = tid >> 5;
    int bx = blockIdx.x;
    int row0 = (bx >> 1) * 128;
    int ch = bx & 1;                  // column half: cols [ch*64, ch*64+64)
    int m0 = wid * 16;

    if (bx == 0 && tid == 0) g_rowcur = 0u;   // reset agg cursor

    if (first) {
        float c = clip_c(curv[l]);
        float K = 1.0f / c;
        float sqrtK = sqrtf(K);
#pragma unroll
        for (int bt = 0; bt < 4; bt++) {
            float4 v[4];
            float ss[4];
#pragma unroll
            for (int j = 0; j < 4; j++) {
                int grow = row0 + m0 + bt * 4 + j;
                v[j] = make_float4(0.f, 0.f, 0.f, 0.f);
                if (grow < N)
                    v[j] = __ldg(reinterpret_cast<const float4*>(
                        xin + (size_t)grow * D) + lane);
            }
#pragma unroll
            for (int j = 0; j < 4; j++)
                ss[j] = v[j].x * v[j].x + v[j].y * v[j].y +
                        v[j].z * v[j].z + v[j].w * v[j].w;
#pragma unroll
            for (int o = 16; o; o >>= 1) {
#pragma unroll
                for (int j = 0; j < 4; j++)
                    ss[j] += __shfl_xor_sync(0xFFFFFFFFu, ss[j], o);
            }
#pragma unroll
            for (int j = 0; j < 4; j++) {
                int row = m0 + bt * 4 + j;
                int grow = row0 + row;
                float xnorm = sqrtf(ss[j]);
                float t = sqrtf(K + ss[j]);
                float theta = acoshf(fmaxf(t / sqrtK, 1.0f + 1e-7f));
                float s = sqrtK * theta / fmaxf(xnorm, 1e-7f);
                float4 u4 = make_float4(v[j].x * s, v[j].y * s,
                                        v[j].z * s, v[j].w * s);
                __half2 h0 = __float22half2_rn(make_float2(u4.x, u4.y));
                __half2 h1 = __float22half2_rn(make_float2(u4.z, u4.w));
                uint2 u;
                u.x = *reinterpret_cast<unsigned*>(&h0);
                u.y = *reinterpret_cast<unsigned*>(&h1);
                if (grow < N)
                    *reinterpret_cast<uint2*>(
                        xt16 + (size_t)grow * (D / 2) + lane * 2) = u;
                *reinterpret_cast<uint2*>(&As[row][lane * 4]) = u;
            }
        }
    } else {
#pragma unroll
        for (int i = 0; i < 16; i++) {
            int row = m0 + i;
            int grow = row0 + row;
            uint2 u = make_uint2(0u, 0u);
            if (grow < N)
                u = __ldg(reinterpret_cast<const uint2*>(
                    xt16 + (size_t)grow * (D / 2)) + lane);
            *reinterpret_cast<uint2*>(&As[row][lane * 4]) = u;
        }
    }

    float acc[8][4];
#pragma unroll
    for (int nt = 0; nt < 8; nt++)
#pragma unroll
        for (int q = 0; q < 4; q++) acc[nt][q] = 0.0f;

    // ldmatrix lane address components
    int a_rr = lane & 7;
    int a_sel = lane >> 3;                  // 0..3
    int a_row = m0 + a_rr + ((a_sel & 1) ? 8 : 0);
    int a_koff = (a_sel >> 1) ? 8 : 0;
    int b_row2 = (lane & 7) + ((lane & 16) ? 8 : 0);
    int b_col2 = (lane & 8) ? 8 : 0;

    // W staging: thread -> row wj (0..63) of this col-half, quarter kq (8 k).
    int wj = tid >> 2;
    int wkq = (tid & 3) * 8;
    const float4* wbase = reinterpret_cast<const float4*>(
        &W[(size_t)(ch * 64 + wj) * D + wkq]);

    // prefetch W chunk 0 (8 floats)
    float4 wreg0 = __ldg(wbase + 0);
    float4 wreg1 = __ldg(wbase + 1);

    for (int kc = 0; kc < 4; kc++) {
        __syncthreads();   // previous Bs consumed; kc=0 also covers As writes
        // store registered W chunk to Bs (fp16)
        {
            __half2 h0 = __float22half2_rn(make_float2(wreg0.x, wreg0.y));
            __half2 h1 = __float22half2_rn(make_float2(wreg0.z, wreg0.w));
            __half2 h2 = __float22half2_rn(make_float2(wreg1.x, wreg1.y));
            __half2 h3 = __float22half2_rn(make_float2(wreg1.z, wreg1.w));
            uint4 u0;
            u0.x = *reinterpret_cast<unsigned*>(&h0);
            u0.y = *reinterpret_cast<unsigned*>(&h1);
            u0.z = *reinterpret_cast<unsigned*>(&h2);
            u0.w = *reinterpret_cast<unsigned*>(&h3);
            *reinterpret_cast<uint4*>(&Bs[wj][wkq]) = u0;
        }
        // prefetch next W chunk (latency overlaps sync + MMA below)
        if (kc < 3) {
            const float4* wp = reinterpret_cast<const float4*>(
                &W[(size_t)(ch * 64 + wj) * D + (kc + 1) * 32 + wkq]);
            wreg0 = __ldg(wp + 0);
            wreg1 = __ldg(wp + 1);
        }
        __syncthreads();

#pragma unroll
        for (int s = 0; s < 2; s++) {
            int kg = kc * 32 + s * 16;      // global k for A
            int ks = s * 16;                // chunk-local k for B
            unsigned a0, a1, a2, a3;
            unsigned aaddr = smem_u32(&As[a_row][kg + a_koff]);
            asm volatile(
                "ldmatrix.sync.aligned.m8n8.x4.shared.b16 {%0,%1,%2,%3}, [%4];"
                : "=r"(a0), "=r"(a1), "=r"(a2), "=r"(a3) : "r"(aaddr));
#pragma unroll
            for (int p = 0; p < 4; p++) {
                unsigned b0, b1, b2, b3;
                unsigned baddr = smem_u32(&Bs[p * 16 + b_row2][ks + b_col2]);
                asm volatile(
                    "ldmatrix.sync.aligned.m8n8.x4.shared.b16 {%0,%1,%2,%3}, [%4];"
                    : "=r"(b0), "=r"(b1), "=r"(b2), "=r"(b3) : "r"(baddr));
                asm volatile(
                    "mma.sync.aligned.m16n8k16.row.col.f32.f16.f16.f32 "
                    "{%0,%1,%2,%3}, {%4,%5,%6,%7}, {%8,%9}, {%0,%1,%2,%3};"
                    : "+f"(acc[2 * p][0]), "+f"(acc[2 * p][1]),
                      "+f"(acc[2 * p][2]), "+f"(acc[2 * p][3])
                    : "r"(a0), "r"(a1), "r"(a2), "r"(a3), "r"(b0), "r"(b1));
                asm volatile(
                    "mma.sync.aligned.m16n8k16.row.col.f32.f16.f16.f32 "
                    "{%0,%1,%2,%3}, {%4,%5,%6,%7}, {%8,%9}, {%0,%1,%2,%3};"
                    : "+f"(acc[2 * p + 1][0]), "+f"(acc[2 * p + 1][1]),
                      "+f"(acc[2 * p + 1][2]), "+f"(acc[2 * p + 1][3])
                    : "r"(a0), "r"(a1), "r"(a2), "r"(a3), "r"(b2), "r"(b3));
            }
        }
    }

    // Epilogue: add bias, convert to fp16, store xl16 (cols ch*64 + ...).
    int gid = lane >> 2;     // C-fragment row group
    int tig = lane & 3;      // C-fragment col pair
    int row1 = row0 + m0 + gid;
    int row2 = row1 + 8;
#pragma unroll
    for (int nt = 0; nt < 8; nt++) {
        int col = ch * 64 + nt * 8 + 2 * tig;
        float2 bv = *reinterpret_cast<const float2*>(&b[col]);
        if (row1 < N) {
            __half2 h = __float22half2_rn(
                make_float2(acc[nt][0] + bv.x, acc[nt][1] + bv.y));
            xl16[(size_t)row1 * (D / 2) + (col >> 1)] = h;
        }
        if (row2 < N) {
            __half2 h = __float22half2_rn(
                make_float2(acc[nt][2] + bv.x, acc[nt][3] + bv.y));
            xl16[(size_t)row2 * (D / 2) + (col >> 1)] = h;
        }
    }
}

// ---------------------------------------------------------------------------
// Fused CSR aggregation (fp16 gather, fp32 accumulate) + mean + residual + LN,
// then expmap (final) or analytic logmap∘expmap (identity when curvatures
// match). FULL warp per row; dynamic 2-row chunks at FULL grid (1184 blocks).
// ---------------------------------------------------------------------------
__global__ void k_aggfinal(const int* __restrict__ incl, const int* __restrict__ bsum,
                           const int* __restrict__ csr,
                           const __half2* __restrict__ xl16,
                           __half2* __restrict__ xt16,
                           const float* __restrict__ gamma, const float* __restrict__ beta,
                           const float* __restrict__ curv, int l,
                           float* __restrict__ out, int N, int final_) {
    int lane = threadIdx.x & 31;
    const uint2* xlu = reinterpret_cast<const uint2*>(xl16);   // 1 uint2 = 4 halves

    float c = clip_c(curv[l]);
    float K = 1.0f / c;
    float sqrtK = sqrtf(K);
    float cnext = final_ ? c : clip_c(curv[l + 1]);
    float4 g = reinterpret_cast<const float4*>(gamma)[lane];
    float4 bb = reinterpret_cast<const float4*>(beta)[lane];

    for (;;) {
        int base;
        if (lane == 0) base = (int)atomicAdd(&g_rowcur, 2u);
        base = __shfl_sync(0xFFFFFFFFu, base, 0);
        if (base >= N) return;
        int wend = base + 2 < N ? base + 2 : N;

        for (int w = base; w < wend; w++) {
            int beg = (w > 0) ? (incl[w - 1] + bsum[(w - 1) >> 8]) : 0;
            int end = incl[w] + bsum[w >> 8];
            float4 acc = make_float4(0.f, 0.f, 0.f, 0.f);

            int e = beg;
            for (; e + 8 <= end; e += 8) {
                int sidx[8];
#pragma unroll
                for (int t = 0; t < 8; t++) sidx[t] = __ldg(&csr[e + t]);
                uint2 q[8];
#pragma unroll
                for (int t = 0; t < 8; t++)
                    q[t] = __ldg(&xlu[(size_t)sidx[t] * 32 + lane]);
#pragma unroll
                for (int t = 0; t < 8; t++) {
                    float2 f0 = __half22float2(*reinterpret_cast<__half2*>(&q[t].x));
                    float2 f1 = __half22float2(*reinterpret_cast<__half2*>(&q[t].y));
                    acc.x += f0.x; acc.y += f0.y; acc.z += f1.x; acc.w += f1.y;
                }
            }
            if (e + 4 <= end) {
                int sidx[4];
#pragma unroll
                for (int t = 0; t < 4; t++) sidx[t] = __ldg(&csr[e + t]);
                uint2 q[4];
#pragma unroll
                for (int t = 0; t < 4; t++)
                    q[t] = __ldg(&xlu[(size_t)sidx[t] * 32 + lane]);
#pragma unroll
                for (int t = 0; t < 4; t++) {
                    float2 f0 = __half22float2(*reinterpret_cast<__half2*>(&q[t].x));
                    float2 f1 = __half22float2(*reinterpret_cast<__half2*>(&q[t].y));
                    acc.x += f0.x; acc.y += f0.y; acc.z += f1.x; acc.w += f1.y;
                }
                e += 4;
            }
            for (; e < end; e++) {
                int s = __ldg(&csr[e]);
                uint2 q = __ldg(&xlu[(size_t)s * 32 + lane]);
                float2 f0 = __half22float2(*reinterpret_cast<__half2*>(&q.x));
                float2 f1 = __half22float2(*reinterpret_cast<__half2*>(&q.y));
                acc.x += f0.x; acc.y += f0.y; acc.z += f1.x; acc.w += f1.y;
            }

            int dg = end - beg;
            float rcn = 1.0f / (float)(dg > 1 ? dg : 1);

            uint2 tu = __ldg(reinterpret_cast<const uint2*>(
                xt16 + (size_t)w * (D / 2)) + lane);
            float2 t0 = __half22float2(*reinterpret_cast<__half2*>(&tu.x));
            float2 t1 = __half22float2(*reinterpret_cast<__half2*>(&tu.y));
            float4 v = make_float4(t0.x + acc.x * rcn, t0.y + acc.y * rcn,
                                   t1.x + acc.z * rcn, t1.y + acc.w * rcn);

            float s1 = v.x + v.y + v.z + v.w;
            float s2 = v.x * v.x + v.y * v.y + v.z * v.z + v.w * v.w;
            s1 = warp_sum(s1);
            s2 = warp_sum(s2);
            float mean = s1 * (1.0f / D);
            float var = s2 * (1.0f / D) - mean * mean;
            float rstd = rsqrtf(var + 1e-5f);

            float4 y = make_float4((v.x - mean) * rstd * g.x + bb.x,
                                   (v.y - mean) * rstd * g.y + bb.y,
                                   (v.z - mean) * rstd * g.z + bb.z,
                                   (v.w - mean) * rstd * g.w + bb.w);

            float ss = y.x * y.x + y.y * y.y + y.z * y.z + y.w * y.w;
            ss = warp_sum(ss);
            float r = sqrtf(ss);

            if (final_) {
                float sc = sqrtK * sinhf(r / sqrtK) / fmaxf(r, 1e-7f);
                float4 o = make_float4(y.x * sc, y.y * sc, y.z * sc, y.w * sc);
                reinterpret_cast<float4*>(out + (size_t)w * D)[lane] = o;
            } else {
                float sc;
                if (c == cnext) {
                    sc = 1.0f;   // logmap_c(expmap_c(y)) == y exactly
                } else {
                    float se = sqrtK * sinhf(r / sqrtK) / fmaxf(r, 1e-7f);
                    float un = se * r;
                    float K1 = 1.0f / cnext;
                    float sk1 = sqrtf(K1);
                    float t = sqrtf(K1 + un * un);
                    float theta = acoshf(fmaxf(t / sk1, 1.0f + 1e-7f));
                    sc = se * sk1 * theta / fmaxf(un, 1e-7f);
                }
                __half2 h0 = __float22half2_rn(make_float2(y.x * sc, y.y * sc));
                __half2 h1 = __float22half2_rn(make_float2(y.z * sc, y.w * sc));
                uint2 u;
                u.x = *reinterpret_cast<unsigned*>(&h0);
                u.y = *reinterpret_cast<unsigned*>(&h1);
                *reinterpret_cast<uint2*>(xt16 + (size_t)w * (D / 2) + lane * 2) = u;
            }
        }
    }
}

// ---------------------------------------------------------------------------
extern "C" void kernel_launch(void* const* d_in, const int* in_sizes, int n_in,
                              void* d_out, int out_size) {
    const float* x_hyp      = (const float*)d_in[0];
    const void*  ei         = d_in[1];
    const float* W          = (const float*)d_in[2];
    const float* b          = (const float*)d_in[3];
    const float* gamma      = (const float*)d_in[4];
    const float* beta       = (const float*)d_in[5];
    const float* curv       = (const float*)d_in[6];

    int N = in_sizes[0] / D;
    int E = in_sizes[1] / 2;
    int L = in_sizes[6];

    __half2 *xl16, *xt16;
    int *deg, *cursor, *incl, *bsum, *csr;
    cudaGetSymbolAddress((void**)&xt16, g_xt16);
    cudaGetSymbolAddress((void**)&xl16, g_xl16);
    cudaGetSymbolAddress((void**)&deg,  g_deg);
    cudaGetSymbolAddress((void**)&cursor, g_cursor);
    cudaGetSymbolAddress((void**)&incl, g_incl);
    cudaGetSymbolAddress((void**)&bsum, g_bsum);
    cudaGetSymbolAddress((void**)&csr,  g_csr);

    int nb = (N + 255) / 256;

    // One-time CSR build: 3 launches (scanB fused into scanA last-block).
    k_hist<<<(E + 255) / 256, 256>>>(ei, deg, E, N);
    k_scanA<<<nb, 256>>>(deg, incl, bsum, cursor, N, nb);
    k_fill<<<(E + 255) / 256, 256>>>(ei, incl, bsum, cursor, csr, E, N);

    int gemmBlocks = 2 * ((N + 127) / 128);   // col-split: 2 blocks per row tile
    for (int l = 0; l < L; l++) {
        k_gemm_fused<<<gemmBlocks, 256>>>(x_hyp, W + (size_t)l * D * D,
                                          b + (size_t)l * D, xt16, xl16,
                                          curv, l, N, l == 0 ? 1 : 0);
        int fin = (l == L - 1) ? 1 : 0;
        k_aggfinal<<<1184, 256>>>(incl, bsum, csr, xl16, xt16,
                                  gamma + (size_t)l * D, beta + (size_t)l * D,
                                  curv, l, (float*)d_out, N, fin);
    }
}

// round 17
// speedup vs baseline: 1.1989x; 1.0469x over previous
#include <cuda_runtime.h>
#include <cuda_fp16.h>
#include <math.h>

#define D 128
#define MAXN 65536
#define MAXE 1100000

// Scratch (allocation-free rule: __device__ globals)
__device__ __half2  g_xt16[MAXN * (D / 2)];
__device__ __half2  g_xl16[MAXN * (D / 2)];
__device__ int      g_deg[MAXN];
__device__ int      g_cursor[MAXN];
__device__ int      g_incl[MAXN];
__device__ int      g_bsum[512];
__device__ int      g_csr[MAXE];
__device__ unsigned g_rowcur;
__device__ unsigned g_done;

__device__ __forceinline__ float warp_sum(float v) {
#pragma unroll
    for (int o = 16; o; o >>= 1) v += __shfl_xor_sync(0xFFFFFFFFu, v, o);
    return v;
}

__device__ __forceinline__ float clip_c(float c) {
    return fminf(fmaxf(c, 0.1f), 10.0f);
}

__device__ __forceinline__ unsigned smem_u32(const void* p) {
    return (unsigned)__cvta_generic_to_shared(p);
}

// Per-block edge-index dtype detection: read first 64 int64 words; if any is
// outside [0,N) the buffer is int32 (misdetect needs 64 consecutive zero
// high-words: p=(1/N)^64 ~ 0). Returns 1 if int64.
__device__ __forceinline__ int detect_is64(const void* ei, int E, long long N) {
    const long long* p64 = (const long long*)ei;
    int n = 2 * E < 128 ? E : 64;
    int bad = 0;
    for (int i = threadIdx.x; i < n; i += 256) {
        long long v = p64[i];
        if (v < 0 || v >= N) bad = 1;
    }
    return !__syncthreads_or(bad);
}

// ---------------------------------------------------------------------------
// In-degree histogram straight from ei (inline dtype detection).
// deg/cursor are pre-zeroed by the PREVIOUS execution's k_scanA (static-init
// zero on the first execution) -> deterministic every replay.
// ---------------------------------------------------------------------------
__global__ void k_hist(const void* __restrict__ ei, int* __restrict__ deg,
                       int E, int N) {
    int is64 = detect_is64(ei, E, (long long)N);
    int e = blockIdx.x * blockDim.x + threadIdx.x;
    if (e >= E) return;
    long long d;
    if (is64) d = ((const long long*)ei)[(size_t)E + e];
    else      d = (long long)((const int*)ei)[(size_t)E + e];
    int di = (int)min(max(d, 0LL), (long long)(N - 1));
    atomicAdd(&deg[di], 1);
}

// ---------------------------------------------------------------------------
// Prefix scan with fused block-sum scan (last-block pattern): per-block
// inclusive scan into incl + block sums into bsum; the LAST block to finish
// scans bsum in place (exclusive) and resets the done counter.
// scanA also re-zeroes deg and cursor so no memset pass.
// rowstart reconstructed by readers: rowstart[g+1] = incl[g] + bsum[g>>8].
// ---------------------------------------------------------------------------
__global__ void k_scanA(int* __restrict__ deg, int* __restrict__ incl,
                        int* __restrict__ bsum, int* __restrict__ cursor,
                        int N, int nb) {
    __shared__ int wsum[8];
    __shared__ bool isLast;
    int tid = threadIdx.x, lane = tid & 31, warp = tid >> 5;
    int gid = blockIdx.x * 256 + tid;
    int v = (gid < N) ? deg[gid] : 0;
    int x = v;
#pragma unroll
    for (int o = 1; o < 32; o <<= 1) {
        int y = __shfl_up_sync(0xFFFFFFFFu, x, o);
        if (lane >= o) x += y;
    }
    if (lane == 31) wsum[warp] = x;
    __syncthreads();
    if (warp == 0) {
        int s = (lane < 8) ? wsum[lane] : 0;
        int y = s;
#pragma unroll
        for (int o = 1; o < 8; o <<= 1) {
            int z = __shfl_up_sync(0xFFFFFFFFu, y, o);
            if (lane >= o) y += z;
        }
        if (lane < 8) wsum[lane] = y - s;   // exclusive warp offset
    }
    __syncthreads();
    int inclv = x + wsum[warp];
    if (gid < N) {
        incl[gid] = inclv;
        deg[gid] = 0;      // pre-zero for next execution's k_hist
        cursor[gid] = 0;   // pre-zero for this execution's k_fill
    }
    if (tid == 255) bsum[blockIdx.x] = inclv;

    // --- last-block tail: scan bsum[0..nb) exclusive, in place ---
    __threadfence();
    if (tid == 0) {
        unsigned prev = atomicAdd(&g_done, 1u);
        isLast = (prev == (unsigned)(gridDim.x - 1));
    }
    __syncthreads();
    if (!isLast) return;
    if (tid == 0) g_done = 0u;   // reset for next replay (deterministic)

    int bv = (tid < nb) ? bsum[tid] : 0;
    int bx = bv;
#pragma unroll
    for (int o = 1; o < 32; o <<= 1) {
        int y = __shfl_up_sync(0xFFFFFFFFu, bx, o);
        if (lane >= o) bx += y;
    }
    __syncthreads();   // reuse wsum
    if (lane == 31) wsum[warp] = bx;
    __syncthreads();
    if (warp == 0) {
        int s = (lane < 8) ? wsum[lane] : 0;
        int y = s;
#pragma unroll
        for (int o = 1; o < 8; o <<= 1) {
            int z = __shfl_up_sync(0xFFFFFFFFu, y, o);
            if (lane >= o) y += z;
        }
        if (lane < 8) wsum[lane] = y - s;
    }
    __syncthreads();
    if (tid < nb) bsum[tid] = bx + wsum[warp] - bv;   // exclusive block offset
}

// ---------------------------------------------------------------------------
// CSR fill straight from ei (inline dtype detection, clamped), rowstart inline.
// ---------------------------------------------------------------------------
__global__ void k_fill(const void* __restrict__ ei,
                       const int* __restrict__ incl, const int* __restrict__ bsum,
                       int* __restrict__ cursor, int* __restrict__ csr,
                       int E, int N) {
    int is64 = detect_is64(ei, E, (long long)N);
    int e = blockIdx.x * blockDim.x + threadIdx.x;
    if (e >= E) return;
    long long s, d;
    if (is64) {
        const long long* p = (const long long*)ei;
        s = p[e];
        d = p[(size_t)E + e];
    } else {
        const int* p = (const int*)ei;
        s = p[e];
        d = p[(size_t)E + e];
    }
    int si = (int)min(max(s, 0LL), (long long)(N - 1));
    int di = (int)min(max(d, 0LL), (long long)(N - 1));
    int rs = (di > 0) ? (incl[di - 1] + bsum[(di - 1) >> 8]) : 0;
    int pos = rs + atomicAdd(&cursor[di], 1);
    csr[pos] = si;
}

// ---------------------------------------------------------------------------
// Fused (logmap+) HMMA GEMM, COLUMN-SPLIT tiles for occupancy:
// block = 128 rows x 64 cols (bx>>1 = row tile, bx&1 = col half).
// Each warp: 16 rows x 64 cols -> 8 n-tiles = 32 accumulators -> 3 CTAs/SM.
// first=1: fp32 x_hyp + logmap (4-row ILP batches), write xt16 + As.
// first=0: fp16 xt16 straight into As. Bs 64x40 halves (pitch-5 c-free).
// Block 0 thread 0 resets the agg row cursor.
// ---------------------------------------------------------------------------
__global__ void __launch_bounds__(256, 3) k_gemm_fused(
        const float* __restrict__ xin, const float* __restrict__ W,
        const float* __restrict__ b, __half2* __restrict__ xt16,
        __half2* __restrict__ xl16, const float* __restrict__ curv,
        int l, int N, int first) {
    __shared__ __half As[128][136];   // 34816 B
    __shared__ __half Bs[64][40];     //  5120 B  (total ~39 KB)
    int tid = threadIdx.x;
    int lane = tid & 31;
    int wid = tid >> 5;
    int bx = blockIdx.x;
    int row0 = (bx >> 1) * 128;
    int ch = bx & 1;                  // column half: cols [ch*64, ch*64+64)
    int m0 = wid * 16;

    if (bx == 0 && tid == 0) g_rowcur = 0u;   // reset agg cursor

    if (first) {
        float c = clip_c(curv[l]);
        float K = 1.0f / c;
        float sqrtK = sqrtf(K);
#pragma unroll
        for (int bt = 0; bt < 4; bt++) {
            float4 v[4];
            float ss[4];
#pragma unroll
            for (int j = 0; j < 4; j++) {
                int grow = row0 + m0 + bt * 4 + j;
                v[j] = make_float4(0.f, 0.f, 0.f, 0.f);
                if (grow < N)
                    v[j] = __ldg(reinterpret_cast<const float4*>(
                        xin + (size_t)grow * D) + lane);
            }
#pragma unroll
            for (int j = 0; j < 4; j++)
                ss[j] = v[j].x * v[j].x + v[j].y * v[j].y +
                        v[j].z * v[j].z + v[j].w * v[j].w;
#pragma unroll
            for (int o = 16; o; o >>= 1) {
#pragma unroll
                for (int j = 0; j < 4; j++)
                    ss[j] += __shfl_xor_sync(0xFFFFFFFFu, ss[j], o);
            }
#pragma unroll
            for (int j = 0; j < 4; j++) {
                int row = m0 + bt * 4 + j;
                int grow = row0 + row;
                float xnorm = sqrtf(ss[j]);
                float t = sqrtf(K + ss[j]);
                float theta = acoshf(fmaxf(t / sqrtK, 1.0f + 1e-7f));
                float s = sqrtK * theta / fmaxf(xnorm, 1e-7f);
                float4 u4 = make_float4(v[j].x * s, v[j].y * s,
                                        v[j].z * s, v[j].w * s);
                __half2 h0 = __float22half2_rn(make_float2(u4.x, u4.y));
                __half2 h1 = __float22half2_rn(make_float2(u4.z, u4.w));
                uint2 u;
                u.x = *reinterpret_cast<unsigned*>(&h0);
                u.y = *reinterpret_cast<unsigned*>(&h1);
                if (grow < N)
                    *reinterpret_cast<uint2*>(
                        xt16 + (size_t)grow * (D / 2) + lane * 2) = u;
                *reinterpret_cast<uint2*>(&As[row][lane * 4]) = u;
            }
        }
    } else {
#pragma unroll
        for (int i = 0; i < 16; i++) {
            int row = m0 + i;
            int grow = row0 + row;
            uint2 u = make_uint2(0u, 0u);
            if (grow < N)
                u = __ldg(reinterpret_cast<const uint2*>(
                    xt16 + (size_t)grow * (D / 2)) + lane);
            *reinterpret_cast<uint2*>(&As[row][lane * 4]) = u;
        }
    }

    float acc[8][4];
#pragma unroll
    for (int nt = 0; nt < 8; nt++)
#pragma unroll
        for (int q = 0; q < 4; q++) acc[nt][q] = 0.0f;

    // ldmatrix lane address components
    int a_rr = lane & 7;
    int a_sel = lane >> 3;                  // 0..3
    int a_row = m0 + a_rr + ((a_sel & 1) ? 8 : 0);
    int a_koff = (a_sel >> 1) ? 8 : 0;
    int b_row2 = (lane & 7) + ((lane & 16) ? 8 : 0);
    int b_col2 = (lane & 8) ? 8 : 0;

    // W staging: thread -> row wj (0..63) of this col-half, quarter kq (8 k).
    int wj = tid >> 2;
    int wkq = (tid & 3) * 8;
    const float4* wbase = reinterpret_cast<const float4*>(
        &W[(size_t)(ch * 64 + wj) * D + wkq]);

    // prefetch W chunk 0 (8 floats)
    float4 wreg0 = __ldg(wbase + 0);
    float4 wreg1 = __ldg(wbase + 1);

    for (int kc = 0; kc < 4; kc++) {
        __syncthreads();   // previous Bs consumed; kc=0 also covers As writes
        // store registered W chunk to Bs (fp16)
        {
            __half2 h0 = __float22half2_rn(make_float2(wreg0.x, wreg0.y));
            __half2 h1 = __float22half2_rn(make_float2(wreg0.z, wreg0.w));
            __half2 h2 = __float22half2_rn(make_float2(wreg1.x, wreg1.y));
            __half2 h3 = __float22half2_rn(make_float2(wreg1.z, wreg1.w));
            uint4 u0;
            u0.x = *reinterpret_cast<unsigned*>(&h0);
            u0.y = *reinterpret_cast<unsigned*>(&h1);
            u0.z = *reinterpret_cast<unsigned*>(&h2);
            u0.w = *reinterpret_cast<unsigned*>(&h3);
            *reinterpret_cast<uint4*>(&Bs[wj][wkq]) = u0;
        }
        // prefetch next W chunk (latency overlaps sync + MMA below)
        if (kc < 3) {
            const float4* wp = reinterpret_cast<const float4*>(
                &W[(size_t)(ch * 64 + wj) * D + (kc + 1) * 32 + wkq]);
            wreg0 = __ldg(wp + 0);
            wreg1 = __ldg(wp + 1);
        }
        __syncthreads();

#pragma unroll
        for (int s = 0; s < 2; s++) {
            int kg = kc * 32 + s * 16;      // global k for A
            int ks = s * 16;                // chunk-local k for B
            unsigned a0, a1, a2, a3;
            unsigned aaddr = smem_u32(&As[a_row][kg + a_koff]);
            asm volatile(
                "ldmatrix.sync.aligned.m8n8.x4.shared.b16 {%0,%1,%2,%3}, [%4];"
                : "=r"(a0), "=r"(a1), "=r"(a2), "=r"(a3) : "r"(aaddr));
#pragma unroll
            for (int p = 0; p < 4; p++) {
                unsigned b0, b1, b2, b3;
                unsigned baddr = smem_u32(&Bs[p * 16 + b_row2][ks + b_col2]);
                asm volatile(
                    "ldmatrix.sync.aligned.m8n8.x4.shared.b16 {%0,%1,%2,%3}, [%4];"
                    : "=r"(b0), "=r"(b1), "=r"(b2), "=r"(b3) : "r"(baddr));
                asm volatile(
                    "mma.sync.aligned.m16n8k16.row.col.f32.f16.f16.f32 "
                    "{%0,%1,%2,%3}, {%4,%5,%6,%7}, {%8,%9}, {%0,%1,%2,%3};"
                    : "+f"(acc[2 * p][0]), "+f"(acc[2 * p][1]),
                      "+f"(acc[2 * p][2]), "+f"(acc[2 * p][3])
                    : "r"(a0), "r"(a1), "r"(a2), "r"(a3), "r"(b0), "r"(b1));
                asm volatile(
                    "mma.sync.aligned.m16n8k16.row.col.f32.f16.f16.f32 "
                    "{%0,%1,%2,%3}, {%4,%5,%6,%7}, {%8,%9}, {%0,%1,%2,%3};"
                    : "+f"(acc[2 * p + 1][0]), "+f"(acc[2 * p + 1][1]),
                      "+f"(acc[2 * p + 1][2]), "+f"(acc[2 * p + 1][3])
                    : "r"(a0), "r"(a1), "r"(a2), "r"(a3), "r"(b2), "r"(b3));
            }
        }
    }

    // Epilogue: add bias, convert to fp16, store xl16 (cols ch*64 + ...).
    int gid = lane >> 2;     // C-fragment row group
    int tig = lane & 3;      // C-fragment col pair
    int row1 = row0 + m0 + gid;
    int row2 = row1 + 8;
#pragma unroll
    for (int nt = 0; nt < 8; nt++) {
        int col = ch * 64 + nt * 8 + 2 * tig;
        float2 bv = *reinterpret_cast<const float2*>(&b[col]);
        if (row1 < N) {
            __half2 h = __float22half2_rn(
                make_float2(acc[nt][0] + bv.x, acc[nt][1] + bv.y));
            xl16[(size_t)row1 * (D / 2) + (col >> 1)] = h;
        }
        if (row2 < N) {
            __half2 h = __float22half2_rn(
                make_float2(acc[nt][2] + bv.x, acc[nt][3] + bv.y));
            xl16[(size_t)row2 * (D / 2) + (col >> 1)] = h;
        }
    }
}

// ---------------------------------------------------------------------------
// Fused CSR aggregation (fp16 gather, fp32 accumulate) + mean + residual + LN,
// then expmap (final) or analytic logmap∘expmap (identity when curvatures
// match). FULL warp per row; dynamic 2-row chunks at FULL grid (1184 blocks).
// ---------------------------------------------------------------------------
__global__ void k_aggfinal(const int* __restrict__ incl, const int* __restrict__ bsum,
                           const int* __restrict__ csr,
                           const __half2* __restrict__ xl16,
                           __half2* __restrict__ xt16,
                           const float* __restrict__ gamma, const float* __restrict__ beta,
                           const float* __restrict__ curv, int l,
                           float* __restrict__ out, int N, int final_) {
    int lane = threadIdx.x & 31;
    const uint2* xlu = reinterpret_cast<const uint2*>(xl16);   // 1 uint2 = 4 halves

    float c = clip_c(curv[l]);
    float K = 1.0f / c;
    float sqrtK = sqrtf(K);
    float cnext = final_ ? c : clip_c(curv[l + 1]);
    float4 g = reinterpret_cast<const float4*>(gamma)[lane];
    float4 bb = reinterpret_cast<const float4*>(beta)[lane];

    for (;;) {
        int base;
        if (lane == 0) base = (int)atomicAdd(&g_rowcur, 2u);
        base = __shfl_sync(0xFFFFFFFFu, base, 0);
        if (base >= N) return;
        int wend = base + 2 < N ? base + 2 : N;

        for (int w = base; w < wend; w++) {
            int beg = (w > 0) ? (incl[w - 1] + bsum[(w - 1) >> 8]) : 0;
            int end = incl[w] + bsum[w >> 8];
            float4 acc = make_float4(0.f, 0.f, 0.f, 0.f);

            int e = beg;
            for (; e + 8 <= end; e += 8) {
                int sidx[8];
#pragma unroll
                for (int t = 0; t < 8; t++) sidx[t] = __ldg(&csr[e + t]);
                uint2 q[8];
#pragma unroll
                for (int t = 0; t < 8; t++)
                    q[t] = __ldg(&xlu[(size_t)sidx[t] * 32 + lane]);
#pragma unroll
                for (int t = 0; t < 8; t++) {
                    float2 f0 = __half22float2(*reinterpret_cast<__half2*>(&q[t].x));
                    float2 f1 = __half22float2(*reinterpret_cast<__half2*>(&q[t].y));
                    acc.x += f0.x; acc.y += f0.y; acc.z += f1.x; acc.w += f1.y;
                }
            }
            if (e + 4 <= end) {
                int sidx[4];
#pragma unroll
                for (int t = 0; t < 4; t++) sidx[t] = __ldg(&csr[e + t]);
                uint2 q[4];
#pragma unroll
                for (int t = 0; t < 4; t++)
                    q[t] = __ldg(&xlu[(size_t)sidx[t] * 32 + lane]);
#pragma unroll
                for (int t = 0; t < 4; t++) {
                    float2 f0 = __half22float2(*reinterpret_cast<__half2*>(&q[t].x));
                    float2 f1 = __half22float2(*reinterpret_cast<__half2*>(&q[t].y));
                    acc.x += f0.x; acc.y += f0.y; acc.z += f1.x; acc.w += f1.y;
                }
                e += 4;
            }
            for (; e < end; e++) {
                int s = __ldg(&csr[e]);
                uint2 q = __ldg(&xlu[(size_t)s * 32 + lane]);
                float2 f0 = __half22float2(*reinterpret_cast<__half2*>(&q.x));
                float2 f1 = __half22float2(*reinterpret_cast<__half2*>(&q.y));
                acc.x += f0.x; acc.y += f0.y; acc.z += f1.x; acc.w += f1.y;
            }

            int dg = end - beg;
            float rcn = 1.0f / (float)(dg > 1 ? dg : 1);

            uint2 tu = __ldg(reinterpret_cast<const uint2*>(
                xt16 + (size_t)w * (D / 2)) + lane);
            float2 t0 = __half22float2(*reinterpret_cast<__half2*>(&tu.x));
            float2 t1 = __half22float2(*reinterpret_cast<__half2*>(&tu.y));
            float4 v = make_float4(t0.x + acc.x * rcn, t0.y + acc.y * rcn,
                                   t1.x + acc.z * rcn, t1.y + acc.w * rcn);

            float s1 = v.x + v.y + v.z + v.w;
            float s2 = v.x * v.x + v.y * v.y + v.z * v.z + v.w * v.w;
            s1 = warp_sum(s1);
            s2 = warp_sum(s2);
            float mean = s1 * (1.0f / D);
            float var = s2 * (1.0f / D) - mean * mean;
            float rstd = rsqrtf(var + 1e-5f);

            float4 y = make_float4((v.x - mean) * rstd * g.x + bb.x,
                                   (v.y - mean) * rstd * g.y + bb.y,
                                   (v.z - mean) * rstd * g.z + bb.z,
                                   (v.w - mean) * rstd * g.w + bb.w);

            float ss = y.x * y.x + y.y * y.y + y.z * y.z + y.w * y.w;
            ss = warp_sum(ss);
            float r = sqrtf(ss);

            if (final_) {
                float sc = sqrtK * sinhf(r / sqrtK) / fmaxf(r, 1e-7f);
                float4 o = make_float4(y.x * sc, y.y * sc, y.z * sc, y.w * sc);
                reinterpret_cast<float4*>(out + (size_t)w * D)[lane] = o;
            } else {
                float sc;
                if (c == cnext) {
                    sc = 1.0f;   // logmap_c(expmap_c(y)) == y exactly
                } else {
                    float se = sqrtK * sinhf(r / sqrtK) / fmaxf(r, 1e-7f);
                    float un = se * r;
                    float K1 = 1.0f / cnext;
                    float sk1 = sqrtf(K1);
                    float t = sqrtf(K1 + un * un);
                    float theta = acoshf(fmaxf(t / sk1, 1.0f + 1e-7f));
                    sc = se * sk1 * theta / fmaxf(un, 1e-7f);
                }
                __half2 h0 = __float22half2_rn(make_float2(y.x * sc, y.y * sc));
                __half2 h1 = __float22half2_rn(make_float2(y.z * sc, y.w * sc));
                uint2 u;
                u.x = *reinterpret_cast<unsigned*>(&h0);
                u.y = *reinterpret_cast<unsigned*>(&h1);
                *reinterpret_cast<uint2*>(xt16 + (size_t)w * (D / 2) + lane * 2) = u;
            }
        }
    }
}

// ---------------------------------------------------------------------------
extern "C" void kernel_launch(void* const* d_in, const int* in_sizes, int n_in,
                              void* d_out, int out_size) {
    const float* x_hyp      = (const float*)d_in[0];
    const void*  ei         = d_in[1];
    const float* W          = (const float*)d_in[2];
    const float* b          = (const float*)d_in[3];
    const float* gamma      = (const float*)d_in[4];
    const float* beta       = (const float*)d_in[5];
    const float* curv       = (const float*)d_in[6];

    int N = in_sizes[0] / D;
    int E = in_sizes[1] / 2;
    int L = in_sizes[6];

    __half2 *xl16, *xt16;
    int *deg, *cursor, *incl, *bsum, *csr;
    cudaGetSymbolAddress((void**)&xt16, g_xt16);
    cudaGetSymbolAddress((void**)&xl16, g_xl16);
    cudaGetSymbolAddress((void**)&deg,  g_deg);
    cudaGetSymbolAddress((void**)&cursor, g_cursor);
    cudaGetSymbolAddress((void**)&incl, g_incl);
    cudaGetSymbolAddress((void**)&bsum, g_bsum);
    cudaGetSymbolAddress((void**)&csr,  g_csr);

    int nb = (N + 255) / 256;
    int gemmBlocks = 2 * ((N + 127) / 128);   // col-split: 2 blocks per row tile

    // Fork the CSR build onto a second stream: it is independent of the
    // layer-0 GEMM (which reads only x_hyp/W/b), and is joined before the
    // layer-0 aggregation. Stream/events are host-side resources created and
    // destroyed every call (no device memory, deterministic, capture-safe
    // fork/join via events).
    cudaStream_t s2;
    cudaEvent_t evFork, evJoin;
    cudaStreamCreateWithFlags(&s2, cudaStreamNonBlocking);
    cudaEventCreateWithFlags(&evFork, cudaEventDisableTiming);
    cudaEventCreateWithFlags(&evJoin, cudaEventDisableTiming);

    cudaEventRecord(evFork, 0);
    cudaStreamWaitEvent(s2, evFork, 0);

    // CSR build on s2 (3 launches, ~30us) ...
    k_hist<<<(E + 255) / 256, 256, 0, s2>>>(ei, deg, E, N);
    k_scanA<<<nb, 256, 0, s2>>>(deg, incl, bsum, cursor, N, nb);
    k_fill<<<(E + 255) / 256, 256, 0, s2>>>(ei, incl, bsum, cursor, csr, E, N);
    cudaEventRecord(evJoin, s2);

    // ... overlapped with layer-0 GEMM on the main stream.
    k_gemm_fused<<<gemmBlocks, 256>>>(x_hyp, W, b, xt16, xl16, curv, 0, N, 1);

    // Join: agg layer 0 needs the CSR.
    cudaStreamWaitEvent(0, evJoin, 0);

    for (int l = 0; l < L; l++) {
        if (l > 0)
            k_gemm_fused<<<gemmBlocks, 256>>>(x_hyp, W + (size_t)l * D * D,
                                              b + (size_t)l * D, xt16, xl16,
                                              curv, l, N, 0);
        int fin = (l == L - 1) ? 1 : 0;
        k_aggfinal<<<1184, 256>>>(incl, bsum, csr, xl16, xt16,
                                  gamma + (size_t)l * D, beta + (size_t)l * D,
                                  curv, l, (float*)d_out, N, fin);
    }

    cudaEventDestroy(evFork);
    cudaEventDestroy(evJoin);
    cudaStreamDestroy(s2);
}